// round 1
// baseline (speedup 1.0000x reference)
#include <cuda_runtime.h>
#include <math.h>

// Problem constants (fixed shapes)
#define T_  4096   // B*S tokens
#define D_  2048   // model dim
#define E_  8      // experts
#define H_  704    // hidden dim
// K (num_selects) = 2, hardcoded

// ---------------- device scratch (static globals; no runtime allocation) ----
__device__ int   g_cnt[E_];            // tokens routed to each expert
__device__ float g_imp[E_];            // importance (sum of scores)
__device__ int   g_load[E_];           // load (count)
__device__ int   g_tok[E_ * T_];       // token index lists per expert
__device__ float g_wt [E_ * T_];       // routing weight lists per expert
__device__ __align__(16) float g_H[(size_t)E_ * T_ * H_];  // SwiGLU hidden scratch

// ---------------------------------------------------------------- init ------
__global__ void init_counters_kernel() {
    int i = threadIdx.x;
    if (i < E_) { g_cnt[i] = 0; g_imp[i] = 0.f; g_load[i] = 0; }
}

__global__ void zero_y_kernel(float4* __restrict__ y) {
    int i = blockIdx.x * blockDim.x + threadIdx.x;
    y[i] = make_float4(0.f, 0.f, 0.f, 0.f);
}

// ---------------------------------------------------------------- gate ------
// One warp per token: logits = tanh(x @ Wg1) @ Wg2, top-2, softmax,
// scatter into per-expert lists, accumulate importance/load.
__global__ void gate_kernel(const float* __restrict__ x,
                            const float* __restrict__ Wg1,
                            const float* __restrict__ Wg2) {
    int t    = (blockIdx.x * blockDim.x + threadIdx.x) >> 5;
    int lane = threadIdx.x & 31;
    if (t >= T_) return;

    const float* xr = x + (size_t)t * D_;
    float acc[E_];
#pragma unroll
    for (int j = 0; j < E_; j++) acc[j] = 0.f;

    for (int i = lane; i < D_; i += 32) {
        float xv = xr[i];
        const float* w = Wg1 + i * E_;
#pragma unroll
        for (int j = 0; j < E_; j++) acc[j] = fmaf(xv, w[j], acc[j]);
    }
#pragma unroll
    for (int j = 0; j < E_; j++) {
#pragma unroll
        for (int off = 16; off; off >>= 1)
            acc[j] += __shfl_xor_sync(0xffffffffu, acc[j], off);
    }

    if (lane == 0) {
        float h1[E_];
#pragma unroll
        for (int i = 0; i < E_; i++) h1[i] = tanhf(acc[i]);
        float lg[E_];
#pragma unroll
        for (int j = 0; j < E_; j++) {
            float s = 0.f;
#pragma unroll
            for (int i = 0; i < E_; i++) s = fmaf(h1[i], Wg2[i * E_ + j], s);
            lg[j] = s;
        }
        // top-2 (strict > keeps lowest index on ties, matching jax top_k)
        int i0 = 0; float v0 = lg[0];
#pragma unroll
        for (int j = 1; j < E_; j++) if (lg[j] > v0) { v0 = lg[j]; i0 = j; }
        int i1 = -1; float v1 = -3.4e38f;
#pragma unroll
        for (int j = 0; j < E_; j++)
            if (j != i0 && lg[j] > v1) { v1 = lg[j]; i1 = j; }

        // softmax over [v0, v1], v0 >= v1
        float e1 = expf(v1 - v0);
        float inv = 1.f / (1.f + e1);
        float w0 = inv, w1 = e1 * inv;

        int s0 = atomicAdd(&g_cnt[i0], 1);
        g_tok[i0 * T_ + s0] = t;  g_wt[i0 * T_ + s0] = w0;
        int s1 = atomicAdd(&g_cnt[i1], 1);
        g_tok[i1 * T_ + s1] = t;  g_wt[i1 * T_ + s1] = w1;

        atomicAdd(&g_imp[i0], w0);  atomicAdd(&g_imp[i1], w1);
        atomicAdd(&g_load[i0], 1);  atomicAdd(&g_load[i1], 1);
    }
}

// ---------------------------------------------------------------- loss ------
__global__ void loss_kernel(float* __restrict__ out_loss) {
    if (threadIdx.x != 0) return;
    float mi = 0.f, ml = 0.f;
#pragma unroll
    for (int e = 0; e < E_; e++) { mi += g_imp[e]; ml += (float)g_load[e]; }
    mi *= (1.f / E_); ml *= (1.f / E_);
    float vi = 0.f, vl = 0.f;
#pragma unroll
    for (int e = 0; e < E_; e++) {
        float di = g_imp[e] - mi;          vi += di * di;
        float dl = (float)g_load[e] - ml;  vl += dl * dl;
    }
    vi *= (1.f / (E_ - 1));  vl *= (1.f / (E_ - 1));   // ddof=1
    float loss = 0.01f * (vi / (mi * mi + 1e-10f) + vl / (ml * ml + 1e-10f));
    *out_loss = loss;
}

// ------------------------------------------------- expert GEMM 1 + SwiGLU ---
// For expert e: G = Xg @ W_gate[e], U = Xg @ W_up[e]  (Xg gathered rows of x)
// H = silu(G) * U  -> g_H[e][slot][:]
// Tiles: 64x64, BK=16, 256 threads, 4x4 microtile (for both G and U).
__global__ __launch_bounds__(256)
void expert_gemm1_kernel(const float* __restrict__ x,
                         const float* __restrict__ Wg,
                         const float* __restrict__ Wu) {
    const int e  = blockIdx.z;
    const int ne = g_cnt[e];
    const int m0 = blockIdx.y * 64;
    if (m0 >= ne) return;
    const int n0 = blockIdx.x * 64;

    __shared__ float As [16][65];
    __shared__ float Bgs[16][64];
    __shared__ float Bus[16][64];

    const int tid = threadIdx.x;
    const int tx  = tid & 15, ty = tid >> 4;

    // A-load mapping: each thread loads float4 of one row
    const int lm  = tid >> 2;          // tile row 0..63
    const int lk4 = (tid & 3) * 4;     // k offset within tile {0,4,8,12}
    const int* toks = g_tok + e * T_;
    int gm = m0 + lm; if (gm > ne - 1) gm = ne - 1;
    const float* arow = x + (size_t)toks[gm] * D_;

    // B-load mapping: row = tid>>4 (0..15), col group = (tid&15)*4
    const size_t boff = (size_t)e * D_ * H_ + (size_t)(tid >> 4) * H_ + n0 + (tid & 15) * 4;
    const float* bg = Wg + boff;
    const float* bu = Wu + boff;

    float accg[16], accu[16];
#pragma unroll
    for (int i = 0; i < 16; i++) { accg[i] = 0.f; accu[i] = 0.f; }

    for (int kt = 0; kt < D_ / 16; ++kt) {
        float4 av = *(const float4*)(arow + kt * 16 + lk4);
        float4 g4 = *(const float4*)(bg + (size_t)kt * 16 * H_);
        float4 u4 = *(const float4*)(bu + (size_t)kt * 16 * H_);
        __syncthreads();
        As[lk4 + 0][lm] = av.x;  As[lk4 + 1][lm] = av.y;
        As[lk4 + 2][lm] = av.z;  As[lk4 + 3][lm] = av.w;
        *(float4*)&Bgs[tid >> 4][(tid & 15) * 4] = g4;
        *(float4*)&Bus[tid >> 4][(tid & 15) * 4] = u4;
        __syncthreads();
#pragma unroll
        for (int kk = 0; kk < 16; ++kk) {
            float a[4], bgv[4], buv[4];
#pragma unroll
            for (int i = 0; i < 4; i++) a[i] = As[kk][ty * 4 + i];
#pragma unroll
            for (int j = 0; j < 4; j++) { bgv[j] = Bgs[kk][tx * 4 + j];
                                          buv[j] = Bus[kk][tx * 4 + j]; }
#pragma unroll
            for (int i = 0; i < 4; i++)
#pragma unroll
                for (int j = 0; j < 4; j++) {
                    accg[i * 4 + j] = fmaf(a[i], bgv[j], accg[i * 4 + j]);
                    accu[i * 4 + j] = fmaf(a[i], buv[j], accu[i * 4 + j]);
                }
        }
    }

    const size_t hb = (size_t)e * T_ * H_;
#pragma unroll
    for (int i = 0; i < 4; i++) {
        int m = m0 + ty * 4 + i;
        if (m < ne) {
            float* hrow = g_H + hb + (size_t)m * H_ + n0 + tx * 4;
#pragma unroll
            for (int j = 0; j < 4; j++) {
                float gv = accg[i * 4 + j];
                float uv = accu[i * 4 + j];
                float sv = gv / (1.f + expf(-gv));   // silu
                hrow[j] = sv * uv;
            }
        }
    }
}

// ------------------------------------------------- expert GEMM 2 + scatter --
// For expert e: EO = H @ W_down[e]; y[tok] += w * EO_row (atomic)
__global__ __launch_bounds__(256)
void expert_gemm2_kernel(const float* __restrict__ Wd,
                         float* __restrict__ y) {
    const int e  = blockIdx.z;
    const int ne = g_cnt[e];
    const int m0 = blockIdx.y * 64;
    if (m0 >= ne) return;
    const int n0 = blockIdx.x * 64;

    __shared__ float As[16][65];
    __shared__ float Bs[16][64];

    const int tid = threadIdx.x;
    const int tx  = tid & 15, ty = tid >> 4;

    const int lm  = tid >> 2;
    const int lk4 = (tid & 3) * 4;
    int gm = m0 + lm; if (gm > ne - 1) gm = ne - 1;
    const float* arow = g_H + ((size_t)e * T_ + gm) * H_;

    const float* bp = Wd + (size_t)e * H_ * D_ + (size_t)(tid >> 4) * D_ + n0 + (tid & 15) * 4;

    float acc[16];
#pragma unroll
    for (int i = 0; i < 16; i++) acc[i] = 0.f;

    for (int kt = 0; kt < H_ / 16; ++kt) {
        float4 av = *(const float4*)(arow + kt * 16 + lk4);
        float4 bv = *(const float4*)(bp + (size_t)kt * 16 * D_);
        __syncthreads();
        As[lk4 + 0][lm] = av.x;  As[lk4 + 1][lm] = av.y;
        As[lk4 + 2][lm] = av.z;  As[lk4 + 3][lm] = av.w;
        *(float4*)&Bs[tid >> 4][(tid & 15) * 4] = bv;
        __syncthreads();
#pragma unroll
        for (int kk = 0; kk < 16; ++kk) {
            float a[4], b[4];
#pragma unroll
            for (int i = 0; i < 4; i++) a[i] = As[kk][ty * 4 + i];
#pragma unroll
            for (int j = 0; j < 4; j++) b[j] = Bs[kk][tx * 4 + j];
#pragma unroll
            for (int i = 0; i < 4; i++)
#pragma unroll
                for (int j = 0; j < 4; j++)
                    acc[i * 4 + j] = fmaf(a[i], b[j], acc[i * 4 + j]);
        }
    }

    const int* toks = g_tok + e * T_;
    const float* wts = g_wt + e * T_;
#pragma unroll
    for (int i = 0; i < 4; i++) {
        int m = m0 + ty * 4 + i;
        if (m < ne) {
            int   tok = toks[m];
            float w   = wts[m];
            float* yr = y + (size_t)tok * D_ + n0 + tx * 4;
#pragma unroll
            for (int j = 0; j < 4; j++)
                atomicAdd(yr + j, w * acc[i * 4 + j]);
        }
    }
}

// ---------------------------------------------------------------- launch ----
extern "C" void kernel_launch(void* const* d_in, const int* in_sizes, int n_in,
                              void* d_out, int out_size) {
    const float* x     = (const float*)d_in[0];
    const float* Wg1   = (const float*)d_in[1];
    const float* Wg2   = (const float*)d_in[2];
    const float* Wgate = (const float*)d_in[3];
    const float* Wup   = (const float*)d_in[4];
    const float* Wdown = (const float*)d_in[5];
    float* y = (float*)d_out;

    init_counters_kernel<<<1, 32>>>();
    zero_y_kernel<<<(T_ * D_ / 4) / 256, 256>>>((float4*)y);
    gate_kernel<<<T_ / 8, 256>>>(x, Wg1, Wg2);
    if (out_size > T_ * D_)
        loss_kernel<<<1, 1>>>(y + (out_size - 1));
    expert_gemm1_kernel<<<dim3(H_ / 64, T_ / 64, E_), 256>>>(x, Wgate, Wup);
    expert_gemm2_kernel<<<dim3(D_ / 64, T_ / 64, E_), 256>>>(Wdown, y);
}

// round 3
// speedup vs baseline: 2.6528x; 2.6528x over previous
#include <cuda_runtime.h>
#include <math.h>
#include <stdint.h>

#define T_  4096   // B*S tokens
#define D_  2048   // model dim
#define E_  8      // experts
#define H_  704    // hidden dim

// ---------------- device scratch ----------------
__device__ int   g_cnt[E_];
__device__ float g_imp[E_];
__device__ int   g_load[E_];
__device__ int   g_tok[E_ * T_];
__device__ float g_wt [E_ * T_];
__device__ __align__(16) float g_H[(size_t)E_ * T_ * H_];

// ---------------- helpers ----------------
__device__ __forceinline__ uint32_t smem_u32(const void* p) {
    uint32_t a;
    asm("{ .reg .u64 t; cvta.to.shared.u64 t, %1; cvt.u32.u64 %0, t; }" : "=r"(a) : "l"(p));
    return a;
}
__device__ __forceinline__ uint32_t f2tf(float f) {
    uint32_t r;
    asm("cvt.rna.tf32.f32 %0, %1;" : "=r"(r) : "f"(f));
    return r;
}
__device__ __forceinline__ void mma_tf32(float* c, const uint32_t* a, const uint32_t* b) {
    asm volatile(
        "mma.sync.aligned.m16n8k8.row.col.f32.tf32.tf32.f32 "
        "{%0,%1,%2,%3}, {%4,%5,%6,%7}, {%8,%9}, {%0,%1,%2,%3};"
        : "+f"(c[0]), "+f"(c[1]), "+f"(c[2]), "+f"(c[3])
        : "r"(a[0]), "r"(a[1]), "r"(a[2]), "r"(a[3]), "r"(b[0]), "r"(b[1]));
}
#define CP16(sa, ga)  asm volatile("cp.async.cg.shared.global [%0], [%1], 16;" :: "r"(sa), "l"(ga))
#define CP_COMMIT()   asm volatile("cp.async.commit_group;" ::: "memory")
#define CP_WAIT1()    asm volatile("cp.async.wait_group 1;" ::: "memory")

// ---------------- small kernels ----------------
__global__ void init_counters_kernel() {
    int i = threadIdx.x;
    if (i < E_) { g_cnt[i] = 0; g_imp[i] = 0.f; g_load[i] = 0; }
}

__global__ void zero_y_kernel(float4* __restrict__ y) {
    int i = blockIdx.x * blockDim.x + threadIdx.x;
    y[i] = make_float4(0.f, 0.f, 0.f, 0.f);
}

__global__ void gate_kernel(const float* __restrict__ x,
                            const float* __restrict__ Wg1,
                            const float* __restrict__ Wg2) {
    int t    = (blockIdx.x * blockDim.x + threadIdx.x) >> 5;
    int lane = threadIdx.x & 31;
    if (t >= T_) return;

    const float* xr = x + (size_t)t * D_;
    float acc[E_];
#pragma unroll
    for (int j = 0; j < E_; j++) acc[j] = 0.f;
    for (int i = lane; i < D_; i += 32) {
        float xv = xr[i];
        const float* w = Wg1 + i * E_;
#pragma unroll
        for (int j = 0; j < E_; j++) acc[j] = fmaf(xv, w[j], acc[j]);
    }
#pragma unroll
    for (int j = 0; j < E_; j++) {
#pragma unroll
        for (int off = 16; off; off >>= 1)
            acc[j] += __shfl_xor_sync(0xffffffffu, acc[j], off);
    }
    if (lane == 0) {
        float h1[E_], lg[E_];
#pragma unroll
        for (int i = 0; i < E_; i++) h1[i] = tanhf(acc[i]);
#pragma unroll
        for (int j = 0; j < E_; j++) {
            float s = 0.f;
#pragma unroll
            for (int i = 0; i < E_; i++) s = fmaf(h1[i], Wg2[i * E_ + j], s);
            lg[j] = s;
        }
        int i0 = 0; float v0 = lg[0];
#pragma unroll
        for (int j = 1; j < E_; j++) if (lg[j] > v0) { v0 = lg[j]; i0 = j; }
        int i1 = -1; float v1 = -3.4e38f;
#pragma unroll
        for (int j = 0; j < E_; j++)
            if (j != i0 && lg[j] > v1) { v1 = lg[j]; i1 = j; }
        float e1 = expf(v1 - v0);
        float inv = 1.f / (1.f + e1);
        float w0 = inv, w1 = e1 * inv;
        int s0 = atomicAdd(&g_cnt[i0], 1);
        g_tok[i0 * T_ + s0] = t;  g_wt[i0 * T_ + s0] = w0;
        int s1 = atomicAdd(&g_cnt[i1], 1);
        g_tok[i1 * T_ + s1] = t;  g_wt[i1 * T_ + s1] = w1;
        atomicAdd(&g_imp[i0], w0);  atomicAdd(&g_imp[i1], w1);
        atomicAdd(&g_load[i0], 1);  atomicAdd(&g_load[i1], 1);
    }
}

__global__ void loss_kernel(float* __restrict__ out_loss) {
    if (threadIdx.x != 0) return;
    float mi = 0.f, ml = 0.f;
#pragma unroll
    for (int e = 0; e < E_; e++) { mi += g_imp[e]; ml += (float)g_load[e]; }
    mi *= (1.f / E_); ml *= (1.f / E_);
    float vi = 0.f, vl = 0.f;
#pragma unroll
    for (int e = 0; e < E_; e++) {
        float di = g_imp[e] - mi;          vi += di * di;
        float dl = (float)g_load[e] - ml;  vl += dl * dl;
    }
    vi *= (1.f / (E_ - 1));  vl *= (1.f / (E_ - 1));
    *out_loss = 0.01f * (vi / (mi * mi + 1e-10f) + vl / (ml * ml + 1e-10f));
}

// ====================== GEMM1: x(gather) @ [Wg|Wu] -> silu*u -> g_H =========
// CTA 128x64, BK=32, 256 thr (warp grid 4Mx2N, warp tile 32x32), tf32 mma.
// smem: [0..512) s_tok, stages at 1024.
// A tile: 128 rows x stride 36 floats (144 B) = 18432 B
// B tiles (gate, up): 32 k x stride 72 floats (288 B) = 9216 B each
#define G1_STAGE 36864
#define G1_SMEM  (1024 + 2 * G1_STAGE)

__global__ void __launch_bounds__(256) xp_gemm1(const float* __restrict__ x,
                                                const float* __restrict__ Wg,
                                                const float* __restrict__ Wu) {
    const int e  = blockIdx.z;
    const int ne = g_cnt[e];
    const int m0 = blockIdx.y * 128;
    if (m0 >= ne) return;
    const int n0 = blockIdx.x * 64;

    extern __shared__ __align__(16) char sm[];
    const uint32_t smb = smem_u32(sm);
    const int tid  = threadIdx.x;
    const int lane = tid & 31;
    const int wid  = tid >> 5;
    const int warpM = wid >> 1, warpN = wid & 1;

    int* s_tok = (int*)sm;
    if (tid < 128) {
        int gm = m0 + tid; if (gm > ne - 1) gm = ne - 1;
        s_tok[tid] = g_tok[e * T_ + gm];
    }
    __syncthreads();

    // cp.async source pointers / smem offsets
    const float* aptr[4];  uint32_t aoff[4];
#pragma unroll
    for (int j = 0; j < 4; j++) {
        int row = (tid >> 3) + j * 32;
        aptr[j] = x + (size_t)s_tok[row] * D_ + (tid & 7) * 4;
        aoff[j] = row * 144 + (tid & 7) * 16;
    }
    const float* gptr[2]; const float* uptr[2];  uint32_t boff[2];
#pragma unroll
    for (int j = 0; j < 2; j++) {
        int row = (tid >> 4) + j * 16;
        size_t base = (size_t)e * D_ * H_ + (size_t)row * H_ + n0 + (tid & 15) * 4;
        gptr[j] = Wg + base;  uptr[j] = Wu + base;
        boff[j] = row * 288 + (tid & 15) * 16;
    }

    float cg[2][4][4], cu[2][4][4];
#pragma unroll
    for (int a = 0; a < 2; a++)
#pragma unroll
        for (int b = 0; b < 4; b++)
#pragma unroll
            for (int c = 0; c < 4; c++) { cg[a][b][c] = 0.f; cu[a][b][c] = 0.f; }

    // prefetch kt=0
    {
        uint32_t sa = smb + 1024;
#pragma unroll
        for (int j = 0; j < 4; j++) CP16(sa + aoff[j], aptr[j]);
#pragma unroll
        for (int j = 0; j < 2; j++) CP16(sa + 18432 + boff[j], gptr[j]);
#pragma unroll
        for (int j = 0; j < 2; j++) CP16(sa + 27648 + boff[j], uptr[j]);
        CP_COMMIT();
    }

    const int lr = lane >> 2, lc = lane & 3;

#pragma unroll 1
    for (int kt = 0; kt < 64; ++kt) {
        const int buf = kt & 1;
        if (kt + 1 < 64) {
            uint32_t sa = smb + 1024 + (buf ^ 1) * G1_STAGE;
            const size_t go = (size_t)(kt + 1) * 32;
#pragma unroll
            for (int j = 0; j < 4; j++) CP16(sa + aoff[j], aptr[j] + go);
#pragma unroll
            for (int j = 0; j < 2; j++) CP16(sa + 18432 + boff[j], gptr[j] + go * H_);
#pragma unroll
            for (int j = 0; j < 2; j++) CP16(sa + 27648 + boff[j], uptr[j] + go * H_);
        }
        CP_COMMIT();
        CP_WAIT1();
        __syncthreads();

        const float* sA = (const float*)(sm + 1024 + buf * G1_STAGE);
        const float* sG = sA + 18432 / 4;
        const float* sU = sG + 9216 / 4;

#pragma unroll
        for (int ks = 0; ks < 4; ++ks) {
            const int k0 = ks * 8;
            uint32_t A[2][4];
#pragma unroll
            for (int mt = 0; mt < 2; ++mt) {
                int rb = warpM * 32 + mt * 16 + lr;
                A[mt][0] = f2tf(sA[rb * 36 + k0 + lc]);
                A[mt][1] = f2tf(sA[(rb + 8) * 36 + k0 + lc]);
                A[mt][2] = f2tf(sA[rb * 36 + k0 + 4 + lc]);
                A[mt][3] = f2tf(sA[(rb + 8) * 36 + k0 + 4 + lc]);
            }
            uint32_t Bg[4][2], Bu[4][2];
#pragma unroll
            for (int nt = 0; nt < 4; ++nt) {
                int cb = warpN * 32 + nt * 8 + lr;
                Bg[nt][0] = f2tf(sG[(k0 + lc) * 72 + cb]);
                Bg[nt][1] = f2tf(sG[(k0 + 4 + lc) * 72 + cb]);
                Bu[nt][0] = f2tf(sU[(k0 + lc) * 72 + cb]);
                Bu[nt][1] = f2tf(sU[(k0 + 4 + lc) * 72 + cb]);
            }
#pragma unroll
            for (int mt = 0; mt < 2; ++mt)
#pragma unroll
                for (int nt = 0; nt < 4; ++nt) {
                    mma_tf32(cg[mt][nt], A[mt], Bg[nt]);
                    mma_tf32(cu[mt][nt], A[mt], Bu[nt]);
                }
        }
        __syncthreads();
    }

    // epilogue: silu(g) * u -> g_H
#pragma unroll
    for (int mt = 0; mt < 2; ++mt) {
#pragma unroll
        for (int half = 0; half < 2; ++half) {
            int rowl = warpM * 32 + mt * 16 + lr + half * 8;
            int row  = m0 + rowl;
            if (row < ne) {
                float* hp = g_H + ((size_t)e * T_ + row) * H_ + n0 + warpN * 32 + lc * 2;
#pragma unroll
                for (int nt = 0; nt < 4; ++nt) {
                    float g0 = cg[mt][nt][half * 2 + 0], u0 = cu[mt][nt][half * 2 + 0];
                    float g1 = cg[mt][nt][half * 2 + 1], u1 = cu[mt][nt][half * 2 + 1];
                    float2 o;
                    o.x = (g0 / (1.f + expf(-g0))) * u0;
                    o.y = (g1 / (1.f + expf(-g1))) * u1;
                    *(float2*)(hp + nt * 8) = o;
                }
            }
        }
    }
}

// ====================== GEMM2: g_H @ Wd -> weighted scatter into y ==========
#define G2_STAGE 27648
#define G2_SMEM  (1024 + 2 * G2_STAGE)

__global__ void __launch_bounds__(256) xp_gemm2(const float* __restrict__ Wd,
                                                float* __restrict__ y) {
    const int e  = blockIdx.z;
    const int ne = g_cnt[e];
    const int m0 = blockIdx.y * 128;
    if (m0 >= ne) return;
    const int n0 = blockIdx.x * 64;

    extern __shared__ __align__(16) char sm[];
    const uint32_t smb = smem_u32(sm);
    const int tid  = threadIdx.x;
    const int lane = tid & 31;
    const int wid  = tid >> 5;
    const int warpM = wid >> 1, warpN = wid & 1;

    int*   s_tok = (int*)sm;
    float* s_wt  = (float*)(sm + 512);
    if (tid < 128) {
        int gm = m0 + tid; if (gm > ne - 1) gm = ne - 1;
        s_tok[tid] = g_tok[e * T_ + gm];
        s_wt[tid]  = g_wt [e * T_ + gm];
    }
    __syncthreads();

    const float* aptr[4];  uint32_t aoff[4];
#pragma unroll
    for (int j = 0; j < 4; j++) {
        int row = (tid >> 3) + j * 32;
        int gm = m0 + row; if (gm > ne - 1) gm = ne - 1;
        aptr[j] = g_H + ((size_t)e * T_ + gm) * H_ + (tid & 7) * 4;
        aoff[j] = row * 144 + (tid & 7) * 16;
    }
    const float* bptr[2];  uint32_t boff[2];
#pragma unroll
    for (int j = 0; j < 2; j++) {
        int row = (tid >> 4) + j * 16;
        bptr[j] = Wd + (size_t)e * H_ * D_ + (size_t)row * D_ + n0 + (tid & 15) * 4;
        boff[j] = row * 288 + (tid & 15) * 16;
    }

    float cacc[2][4][4];
#pragma unroll
    for (int a = 0; a < 2; a++)
#pragma unroll
        for (int b = 0; b < 4; b++)
#pragma unroll
            for (int c = 0; c < 4; c++) cacc[a][b][c] = 0.f;

    {
        uint32_t sa = smb + 1024;
#pragma unroll
        for (int j = 0; j < 4; j++) CP16(sa + aoff[j], aptr[j]);
#pragma unroll
        for (int j = 0; j < 2; j++) CP16(sa + 18432 + boff[j], bptr[j]);
        CP_COMMIT();
    }

    const int lr = lane >> 2, lc = lane & 3;

#pragma unroll 1
    for (int kt = 0; kt < 22; ++kt) {
        const int buf = kt & 1;
        if (kt + 1 < 22) {
            uint32_t sa = smb + 1024 + (buf ^ 1) * G2_STAGE;
            const size_t go = (size_t)(kt + 1) * 32;
#pragma unroll
            for (int j = 0; j < 4; j++) CP16(sa + aoff[j], aptr[j] + go);
#pragma unroll
            for (int j = 0; j < 2; j++) CP16(sa + 18432 + boff[j], bptr[j] + go * D_);
        }
        CP_COMMIT();
        CP_WAIT1();
        __syncthreads();

        const float* sA = (const float*)(sm + 1024 + buf * G2_STAGE);
        const float* sB = sA + 18432 / 4;

#pragma unroll
        for (int ks = 0; ks < 4; ++ks) {
            const int k0 = ks * 8;
            uint32_t A[2][4];
#pragma unroll
            for (int mt = 0; mt < 2; ++mt) {
                int rb = warpM * 32 + mt * 16 + lr;
                A[mt][0] = f2tf(sA[rb * 36 + k0 + lc]);
                A[mt][1] = f2tf(sA[(rb + 8) * 36 + k0 + lc]);
                A[mt][2] = f2tf(sA[rb * 36 + k0 + 4 + lc]);
                A[mt][3] = f2tf(sA[(rb + 8) * 36 + k0 + 4 + lc]);
            }
            uint32_t B[4][2];
#pragma unroll
            for (int nt = 0; nt < 4; ++nt) {
                int cb = warpN * 32 + nt * 8 + lr;
                B[nt][0] = f2tf(sB[(k0 + lc) * 72 + cb]);
                B[nt][1] = f2tf(sB[(k0 + 4 + lc) * 72 + cb]);
            }
#pragma unroll
            for (int mt = 0; mt < 2; ++mt)
#pragma unroll
                for (int nt = 0; nt < 4; ++nt)
                    mma_tf32(cacc[mt][nt], A[mt], B[nt]);
        }
        __syncthreads();
    }

    // epilogue: y[tok] += w * acc  (atomic)
#pragma unroll
    for (int mt = 0; mt < 2; ++mt) {
#pragma unroll
        for (int half = 0; half < 2; ++half) {
            int rowl = warpM * 32 + mt * 16 + lr + half * 8;
            int row  = m0 + rowl;
            if (row < ne) {
                int   tok = s_tok[rowl];
                float w   = s_wt[rowl];
                float* yp = y + (size_t)tok * D_ + n0 + warpN * 32 + lc * 2;
#pragma unroll
                for (int nt = 0; nt < 4; ++nt) {
                    atomicAdd(yp + nt * 8 + 0, w * cacc[mt][nt][half * 2 + 0]);
                    atomicAdd(yp + nt * 8 + 1, w * cacc[mt][nt][half * 2 + 1]);
                }
            }
        }
    }
}

// ---------------- launch ----------------
extern "C" void kernel_launch(void* const* d_in, const int* in_sizes, int n_in,
                              void* d_out, int out_size) {
    const float* x     = (const float*)d_in[0];
    const float* Wg1   = (const float*)d_in[1];
    const float* Wg2   = (const float*)d_in[2];
    const float* Wgate = (const float*)d_in[3];
    const float* Wup   = (const float*)d_in[4];
    const float* Wdown = (const float*)d_in[5];
    float* y = (float*)d_out;

    cudaFuncSetAttribute(xp_gemm1, cudaFuncAttributeMaxDynamicSharedMemorySize, G1_SMEM);
    cudaFuncSetAttribute(xp_gemm2, cudaFuncAttributeMaxDynamicSharedMemorySize, G2_SMEM);

    init_counters_kernel<<<1, 32>>>();
    zero_y_kernel<<<(T_ * D_ / 4) / 256, 256>>>((float4*)y);
    gate_kernel<<<T_ / 8, 256>>>(x, Wg1, Wg2);
    if (out_size > T_ * D_)
        loss_kernel<<<1, 1>>>(y + (out_size - 1));
    xp_gemm1<<<dim3(H_ / 64, T_ / 128, E_), 256, G1_SMEM>>>(x, Wgate, Wup);
    xp_gemm2<<<dim3(D_ / 64, T_ / 128, E_), 256, G2_SMEM>>>(Wdown, y);
}